// round 2
// baseline (speedup 1.0000x reference)
#include <cuda_runtime.h>
#include <math.h>

#define BB 4
#define SS 2048
#define HH 1024
#define INNERD 512
#define RAD 8
#define KSTEPS 4
#define LAMv 0.1f
#define MU_MAXV 10.0f

#define BSH (BB*SS*HH)

// Scratch (no cudaMalloc allowed)
__device__ float g_q[BSH];
__device__ float g_state[BSH];
__device__ float g_tmp[BSH];
__device__ float g_nsq[BB*SS];
__device__ float g_dots[BB*RAD*SS];
__device__ float g_mu[BB*RAD*SS];
__device__ float g_isq[BB*SS];

// ---------------------------------------------------------------------------
// GEMM: q = hidden @ Wq + bq.  M = B*S = 8192, N = K = 1024. fp32 SIMT tiled.
// ---------------------------------------------------------------------------
#define GT_M 128
#define GT_N 128
#define GT_K 8

__global__ __launch_bounds__(256) void gemm_q_kernel(
    const float* __restrict__ A,   // M x K (hidden)
    const float* __restrict__ W,   // K x N (Wq)
    const float* __restrict__ bias)
{
    const int M = BB*SS, N = HH, K = HH;
    __shared__ float As[GT_K][GT_M + 4];
    __shared__ float Bs[GT_K][GT_N];
    int tid = threadIdx.x;
    int m0 = blockIdx.y * GT_M;
    int n0 = blockIdx.x * GT_N;
    int tm = (tid >> 4) * 8;
    int tn = (tid & 15) * 8;

    int la_m = tid >> 1;
    int la_k = (tid & 1) * 4;
    int lb_k = tid >> 5;
    int lb_n = (tid & 31) * 4;

    float acc[8][8];
#pragma unroll
    for (int i = 0; i < 8; i++)
#pragma unroll
        for (int j = 0; j < 8; j++) acc[i][j] = 0.f;

    for (int k0 = 0; k0 < K; k0 += GT_K) {
        float4 av = *(const float4*)&A[(size_t)(m0 + la_m) * K + k0 + la_k];
        float4 bv = *(const float4*)&W[(size_t)(k0 + lb_k) * N + n0 + lb_n];
        __syncthreads();
        As[la_k + 0][la_m] = av.x;
        As[la_k + 1][la_m] = av.y;
        As[la_k + 2][la_m] = av.z;
        As[la_k + 3][la_m] = av.w;
        *(float4*)&Bs[lb_k][lb_n] = bv;
        __syncthreads();
#pragma unroll
        for (int kk = 0; kk < GT_K; kk++) {
            float4 a0 = *(const float4*)&As[kk][tm];
            float4 a1 = *(const float4*)&As[kk][tm + 4];
            float4 b0 = *(const float4*)&Bs[kk][tn];
            float4 b1 = *(const float4*)&Bs[kk][tn + 4];
            float a[8] = {a0.x,a0.y,a0.z,a0.w,a1.x,a1.y,a1.z,a1.w};
            float b[8] = {b0.x,b0.y,b0.z,b0.w,b1.x,b1.y,b1.z,b1.w};
#pragma unroll
            for (int i = 0; i < 8; i++)
#pragma unroll
                for (int j = 0; j < 8; j++)
                    acc[i][j] = fmaf(a[i], b[j], acc[i][j]);
        }
    }
#pragma unroll
    for (int i = 0; i < 8; i++) {
        float4 o0, o1;
        o0.x = acc[i][0] + bias[n0+tn+0]; o0.y = acc[i][1] + bias[n0+tn+1];
        o0.z = acc[i][2] + bias[n0+tn+2]; o0.w = acc[i][3] + bias[n0+tn+3];
        o1.x = acc[i][4] + bias[n0+tn+4]; o1.y = acc[i][5] + bias[n0+tn+5];
        o1.z = acc[i][6] + bias[n0+tn+6]; o1.w = acc[i][7] + bias[n0+tn+7];
        *(float4*)&g_q[(size_t)(m0+tm+i)*N + n0+tn]     = o0;
        *(float4*)&g_q[(size_t)(m0+tm+i)*N + n0+tn + 4] = o1;
    }
}

// ---------------------------------------------------------------------------
// state = hidden
// ---------------------------------------------------------------------------
__global__ void copy_state_kernel(const float* __restrict__ hidden)
{
    int idx = blockIdx.x * blockDim.x + threadIdx.x;   // over BSH/4
    float4 v = ((const float4*)hidden)[idx];
    ((float4*)g_state)[idx] = v;
}

// ---------------------------------------------------------------------------
// Per node i: nsq[i] = ||s_i||^2 ; dots[d][i] = <s_i, s_{i+d}> for d=1..8
// grid (S, B), 256 threads, 4 elems/thread
// ---------------------------------------------------------------------------
__global__ __launch_bounds__(256) void dots_kernel()
{
    int i = blockIdx.x, b = blockIdx.y;
    int tid = threadIdx.x;
    const float* row = g_state + ((size_t)b * SS + i) * HH;
    float4 a = *(const float4*)(row + tid * 4);
    float acc[RAD + 1];
    acc[0] = a.x*a.x + a.y*a.y + a.z*a.z + a.w*a.w;
#pragma unroll
    for (int d = 1; d <= RAD; d++) {
        if (i + d < SS) {
            float4 c = *(const float4*)(row + (size_t)d * HH + tid * 4);
            acc[d] = a.x*c.x + a.y*c.y + a.z*c.z + a.w*c.w;
        } else acc[d] = 0.f;
    }
#pragma unroll
    for (int k = 0; k <= RAD; k++) {
#pragma unroll
        for (int o = 16; o > 0; o >>= 1)
            acc[k] += __shfl_down_sync(0xffffffffu, acc[k], o);
    }
    __shared__ float red[8][RAD + 1];
    int wid = tid >> 5, lane = tid & 31;
    if (lane == 0)
#pragma unroll
        for (int k = 0; k <= RAD; k++) red[wid][k] = acc[k];
    __syncthreads();
    if (tid <= RAD) {
        float v = 0.f;
#pragma unroll
        for (int w = 0; w < 8; w++) v += red[w][tid];
        if (tid == 0) g_nsq[b * SS + i] = v;
        else if (i + tid < SS) g_dots[((size_t)b * RAD + (tid - 1)) * SS + i] = v;
    }
}

// ---------------------------------------------------------------------------
// Per edge (b,d,i): mu = min(softplus(MLP([dist,cos])) + 1e-5, 10). warp/edge.
// ---------------------------------------------------------------------------
__global__ __launch_bounds__(256) void mu_kernel(
    const float* __restrict__ W1, const float* __restrict__ b1,
    const float* __restrict__ W2, const float* __restrict__ b2)
{
    int gw = (blockIdx.x * blockDim.x + threadIdx.x) >> 5;
    int lane = threadIdx.x & 31;
    if (gw >= BB * RAD * SS) return;
    int b = gw / (RAD * SS);
    int r = gw - b * (RAD * SS);
    int d = r / SS + 1;
    int i = r - (d - 1) * SS;
    size_t slot = ((size_t)b * RAD + (d - 1)) * SS + i;
    if (i + d >= SS) { if (lane == 0) g_mu[slot] = 0.f; return; }
    float nsqi = g_nsq[b * SS + i];
    float nsqj = g_nsq[b * SS + i + d];
    float dot  = g_dots[slot];
    float dist = sqrtf(fmaxf(nsqi + nsqj - 2.f * dot, 0.f));
    float ni = fmaxf(sqrtf(nsqi), 1e-6f);
    float nj = fmaxf(sqrtf(nsqj), 1e-6f);
    float cosv = dot / (ni * nj);
    float acc = 0.f;
#pragma unroll 4
    for (int k = lane; k < INNERD; k += 32) {
        float x = fmaf(dist, W1[k], fmaf(cosv, W1[INNERD + k], b1[k]));
        float g = 0.5f * x * (1.f + erff(x * 0.70710678118654752f));
        acc = fmaf(g, W2[k], acc);
    }
#pragma unroll
    for (int o = 16; o > 0; o >>= 1)
        acc += __shfl_down_sync(0xffffffffu, acc, o);
    if (lane == 0) {
        float z = acc + b2[0];
        float sp = fmaxf(z, 0.f) + log1pf(expf(-fabsf(z)));   // stable softplus
        g_mu[slot] = fminf(sp + 1e-5f, MU_MAXV);
    }
}

// ---------------------------------------------------------------------------
// deg[i] = sum of incident mu ; isq[i] = max(deg,1e-6)^-0.5
// ---------------------------------------------------------------------------
__global__ void deg_kernel()
{
    int i = blockIdx.x * blockDim.x + threadIdx.x;
    int b = blockIdx.y;
    if (i >= SS) return;
    float deg = 0.f;
#pragma unroll
    for (int d = 1; d <= RAD; d++) {
        if (i + d < SS) deg += g_mu[((size_t)b * RAD + (d - 1)) * SS + i];
        if (i >= d)     deg += g_mu[((size_t)b * RAD + (d - 1)) * SS + i - d];
    }
    g_isq[b * SS + i] = 1.f / sqrtf(fmaxf(deg, 1e-6f));
}

// ---------------------------------------------------------------------------
// lap + update: tmp_i = s_i - eta * ( sum_j c_ij (s_i - s_j) - q_i )
// grid (S, B), 256 threads, 4 elems/thread
// ---------------------------------------------------------------------------
__global__ __launch_bounds__(256) void lap_update_kernel(float eta)
{
    int i = blockIdx.x, b = blockIdx.y;
    int tid = threadIdx.x;
    __shared__ float cof[2 * RAD];
    __shared__ int   joff[2 * RAD];
    if (tid < 2 * RAD) {
        int d = (tid >> 1) + 1;
        bool plus = (tid & 1) == 0;
        float c = 0.f; int j = i;
        if (plus) {
            if (i + d < SS) {
                j = i + d;
                c = g_mu[((size_t)b * RAD + (d - 1)) * SS + i] *
                    g_isq[b * SS + i] * g_isq[b * SS + j];
            }
        } else {
            if (i >= d) {
                j = i - d;
                c = g_mu[((size_t)b * RAD + (d - 1)) * SS + j] *
                    g_isq[b * SS + i] * g_isq[b * SS + j];
            }
        }
        cof[tid] = c; joff[tid] = j;
    }
    __syncthreads();
    float csum = 0.f;
#pragma unroll
    for (int k = 0; k < 2 * RAD; k++) csum += cof[k];

    size_t base = ((size_t)b * SS + i) * HH + tid * 4;
    float4 hi = *(const float4*)&g_state[base];
    float4 acc;
    acc.x = csum * hi.x; acc.y = csum * hi.y;
    acc.z = csum * hi.z; acc.w = csum * hi.w;
#pragma unroll
    for (int k = 0; k < 2 * RAD; k++) {
        float c = cof[k];
        if (c != 0.f) {
            float4 hj = *(const float4*)&g_state[((size_t)b * SS + joff[k]) * HH + tid * 4];
            acc.x = fmaf(-c, hj.x, acc.x);
            acc.y = fmaf(-c, hj.y, acc.y);
            acc.z = fmaf(-c, hj.z, acc.z);
            acc.w = fmaf(-c, hj.w, acc.w);
        }
    }
    float4 qv = *(const float4*)&g_q[base];
    float4 nv;
    nv.x = hi.x - eta * (acc.x - qv.x);
    nv.y = hi.y - eta * (acc.y - qv.y);
    nv.z = hi.z - eta * (acc.z - qv.z);
    nv.w = hi.w - eta * (acc.w - qv.w);
    *(float4*)&g_tmp[base] = nv;
}

// ---------------------------------------------------------------------------
// smooth: state_i = tmp_i - lam*(2 tmp_i - tmp_{i-1} - tmp_{i+1}) (clamped)
// ---------------------------------------------------------------------------
__global__ void smooth_kernel()
{
    int idx = blockIdx.x * blockDim.x + threadIdx.x;   // over BSH/4
    int h4 = idx & (HH / 4 - 1);
    int rest = idx >> 8;                                // / (HH/4)
    int i = rest & (SS - 1);
    int b = rest >> 11;                                 // / SS
    int im = (i > 0) ? i - 1 : 0;
    int ip = (i < SS - 1) ? i + 1 : SS - 1;
    size_t rb = (size_t)b * SS;
    float4 s = ((const float4*)g_tmp)[(rb + i)  * (HH/4) + h4];
    float4 l = ((const float4*)g_tmp)[(rb + im) * (HH/4) + h4];
    float4 r = ((const float4*)g_tmp)[(rb + ip) * (HH/4) + h4];
    float4 o;
    o.x = s.x - LAMv * (2.f * s.x - l.x - r.x);
    o.y = s.y - LAMv * (2.f * s.y - l.y - r.y);
    o.z = s.z - LAMv * (2.f * s.z - l.z - r.z);
    o.w = s.w - LAMv * (2.f * s.w - l.w - r.w);
    ((float4*)g_state)[idx] = o;
}

// ---------------------------------------------------------------------------
// energy[b] = 0.5 * sum_e mu_e * (nsq_i + nsq_j - 2 dot_e)   (final state)
// ---------------------------------------------------------------------------
__global__ __launch_bounds__(256) void energy_kernel(float* __restrict__ out)
{
    int b = blockIdx.x;
    int tid = threadIdx.x;
    float partial = 0.f;
    for (int e = tid; e < RAD * SS; e += 256) {
        int d = e / SS + 1;
        int i = e - (d - 1) * SS;
        if (i + d < SS) {
            size_t slot = ((size_t)b * RAD + (d - 1)) * SS + i;
            float mu = g_mu[slot];
            float dsq = g_nsq[b * SS + i] + g_nsq[b * SS + i + d]
                      - 2.f * g_dots[slot];
            partial += mu * dsq;
        }
    }
#pragma unroll
    for (int o = 16; o > 0; o >>= 1)
        partial += __shfl_down_sync(0xffffffffu, partial, o);
    __shared__ float red[8];
    int wid = tid >> 5, lane = tid & 31;
    if (lane == 0) red[wid] = partial;
    __syncthreads();
    if (tid == 0) {
        float s = 0.f;
#pragma unroll
        for (int w = 0; w < 8; w++) s += red[w];
        out[(size_t)BSH + b] = 0.5f * s;
    }
}

// ---------------------------------------------------------------------------
// out = layernorm(state + hidden) * gamma + beta
// ---------------------------------------------------------------------------
__global__ __launch_bounds__(256) void ln_kernel(
    const float* __restrict__ hidden,
    const float* __restrict__ gamma, const float* __restrict__ beta,
    float* __restrict__ out)
{
    int i = blockIdx.x, b = blockIdx.y;
    int tid = threadIdx.x;
    size_t base = ((size_t)b * SS + i) * HH + tid * 4;
    float4 s = *(const float4*)&g_state[base];
    float4 h = *(const float4*)&hidden[base];
    float4 x;
    x.x = s.x + h.x; x.y = s.y + h.y; x.z = s.z + h.z; x.w = s.w + h.w;
    float sum = x.x + x.y + x.z + x.w;
    float sq  = x.x*x.x + x.y*x.y + x.z*x.z + x.w*x.w;
#pragma unroll
    for (int o = 16; o > 0; o >>= 1) {
        sum += __shfl_down_sync(0xffffffffu, sum, o);
        sq  += __shfl_down_sync(0xffffffffu, sq,  o);
    }
    __shared__ float rs[8], rq[8];
    int wid = tid >> 5, lane = tid & 31;
    if (lane == 0) { rs[wid] = sum; rq[wid] = sq; }
    __syncthreads();
    __shared__ float s_mean, s_rstd;
    if (tid == 0) {
        float ts = 0.f, tq = 0.f;
#pragma unroll
        for (int w = 0; w < 8; w++) { ts += rs[w]; tq += rq[w]; }
        float mean = ts / HH;
        float var = tq / HH - mean * mean;
        s_mean = mean;
        s_rstd = rsqrtf(var + 1e-5f);
    }
    __syncthreads();
    float mean = s_mean, rstd = s_rstd;
    int hbase = tid * 4;
    float4 o;
    o.x = (x.x - mean) * rstd * gamma[hbase+0] + beta[hbase+0];
    o.y = (x.y - mean) * rstd * gamma[hbase+1] + beta[hbase+1];
    o.z = (x.z - mean) * rstd * gamma[hbase+2] + beta[hbase+2];
    o.w = (x.w - mean) * rstd * gamma[hbase+3] + beta[hbase+3];
    *(float4*)&out[base] = o;
}

// ---------------------------------------------------------------------------
extern "C" void kernel_launch(void* const* d_in, const int* in_sizes, int n_in,
                              void* d_out, int out_size)
{
    const float* hidden = (const float*)d_in[0];
    // d_in[1]=attention_mask (all ones), d_in[2]=edges (fixed band) — unused
    const float* Wq = (const float*)d_in[3];
    const float* bq = (const float*)d_in[4];
    const float* W1 = (const float*)d_in[5];
    const float* b1 = (const float*)d_in[6];
    const float* W2 = (const float*)d_in[7];
    const float* b2 = (const float*)d_in[8];
    const float* gamma = (const float*)d_in[9];
    const float* beta  = (const float*)d_in[10];
    float* out = (float*)d_out;

    gemm_q_kernel<<<dim3(HH / GT_N, (BB * SS) / GT_M), 256>>>(hidden, Wq, bq);
    copy_state_kernel<<<(BSH / 4) / 256, 256>>>(hidden);

    float eta = 0.1f;
    for (int step = 0; step < KSTEPS; step++) {
        dots_kernel<<<dim3(SS, BB), 256>>>();
        mu_kernel<<<(BB * RAD * SS) / 8, 256>>>(W1, b1, W2, b2);
        deg_kernel<<<dim3(SS / 256, BB), 256>>>();
        lap_update_kernel<<<dim3(SS, BB), 256>>>(eta);
        smooth_kernel<<<(BSH / 4) / 256, 256>>>();
        eta *= 0.9f;
    }
    dots_kernel<<<dim3(SS, BB), 256>>>();   // nsq/dots of FINAL state
    energy_kernel<<<BB, 256>>>(out);
    ln_kernel<<<dim3(SS, BB), 256>>>(hidden, gamma, beta, out);
}

// round 3
// speedup vs baseline: 1.4970x; 1.4970x over previous
#include <cuda_runtime.h>
#include <math.h>
#include <stdint.h>

#define BB 4
#define SS 2048
#define HH 1024
#define INNERD 512
#define RAD 8
#define KSTEPS 4
#define LAMv 0.1f
#define MU_MAXV 10.0f

#define BSH (BB*SS*HH)

// Scratch (no cudaMalloc allowed)
__device__ float g_q[BSH];
__device__ float g_state[BSH];
__device__ float g_nsq[BB*SS];
__device__ float g_dots[BB*RAD*SS];
__device__ float g_mu[BB*RAD*SS];
__device__ float g_isq[BB*SS];

__device__ __forceinline__ float to_tf32(float x) {
    float r;
    asm("cvt.rna.tf32.f32 %0, %1;" : "=f"(r) : "f"(x));
    return r;
}

// ---------------------------------------------------------------------------
// GEMM (TF32 mma.sync): q = hidden @ Wq + bq.  M=8192, N=K=1024.
// Block 128x128, 8 warps, warp 32x64, K-step 32.
// ---------------------------------------------------------------------------
#define TM 128
#define TN 128
#define TK 32

__global__ __launch_bounds__(256) void gemm_tf32_kernel(
    const float* __restrict__ A,
    const float* __restrict__ W,
    const float* __restrict__ bias)
{
    const int N = HH, K = HH;
    __shared__ float As[TK][TM + 4];   // k-major
    __shared__ float Bs[TK][TN + 4];

    int tid = threadIdx.x;
    int m0 = blockIdx.y * TM;
    int n0 = blockIdx.x * TN;
    int wid = tid >> 5, lane = tid & 31;
    int wm = (wid & 3) * 32;
    int wn = (wid >> 2) * 64;
    int gid = lane >> 2, tig = lane & 3;

    float acc[2][8][4];
#pragma unroll
    for (int mt = 0; mt < 2; mt++)
#pragma unroll
        for (int nt = 0; nt < 8; nt++)
#pragma unroll
            for (int c = 0; c < 4; c++) acc[mt][nt][c] = 0.f;

    int a_row = tid >> 3;            // 0..31
    int a_k4  = (tid & 7) * 4;       // 0..28
    int b_k   = tid >> 5;            // 0..7
    int b_n4  = (tid & 31) * 4;      // 0..124

    for (int k0 = 0; k0 < K; k0 += TK) {
        __syncthreads();
#pragma unroll
        for (int r = 0; r < 4; r++) {
            int m = a_row + r * 32;
            float4 v = *(const float4*)&A[(size_t)(m0 + m) * K + k0 + a_k4];
            As[a_k4 + 0][m] = to_tf32(v.x);
            As[a_k4 + 1][m] = to_tf32(v.y);
            As[a_k4 + 2][m] = to_tf32(v.z);
            As[a_k4 + 3][m] = to_tf32(v.w);
        }
#pragma unroll
        for (int r = 0; r < 4; r++) {
            int k = b_k + r * 8;
            float4 v = *(const float4*)&W[(size_t)(k0 + k) * N + n0 + b_n4];
            Bs[k][b_n4 + 0] = to_tf32(v.x);
            Bs[k][b_n4 + 1] = to_tf32(v.y);
            Bs[k][b_n4 + 2] = to_tf32(v.z);
            Bs[k][b_n4 + 3] = to_tf32(v.w);
        }
        __syncthreads();

#pragma unroll
        for (int ks = 0; ks < 4; ks++) {
            int kb = ks * 8;
            uint32_t af[2][4];
#pragma unroll
            for (int mt = 0; mt < 2; mt++) {
                int rm = wm + mt * 16 + gid;
                af[mt][0] = __float_as_uint(As[kb + tig][rm]);
                af[mt][1] = __float_as_uint(As[kb + tig][rm + 8]);
                af[mt][2] = __float_as_uint(As[kb + tig + 4][rm]);
                af[mt][3] = __float_as_uint(As[kb + tig + 4][rm + 8]);
            }
            uint32_t bf[8][2];
#pragma unroll
            for (int nt = 0; nt < 8; nt++) {
                int cn = wn + nt * 8 + gid;
                bf[nt][0] = __float_as_uint(Bs[kb + tig][cn]);
                bf[nt][1] = __float_as_uint(Bs[kb + tig + 4][cn]);
            }
#pragma unroll
            for (int mt = 0; mt < 2; mt++)
#pragma unroll
                for (int nt = 0; nt < 8; nt++) {
                    asm volatile(
                        "mma.sync.aligned.m16n8k8.row.col.f32.tf32.tf32.f32 "
                        "{%0,%1,%2,%3}, {%4,%5,%6,%7}, {%8,%9}, {%0,%1,%2,%3};"
                        : "+f"(acc[mt][nt][0]), "+f"(acc[mt][nt][1]),
                          "+f"(acc[mt][nt][2]), "+f"(acc[mt][nt][3])
                        : "r"(af[mt][0]), "r"(af[mt][1]),
                          "r"(af[mt][2]), "r"(af[mt][3]),
                          "r"(bf[nt][0]), "r"(bf[nt][1]));
                }
        }
    }

#pragma unroll
    for (int mt = 0; mt < 2; mt++) {
        int row0 = m0 + wm + mt * 16 + gid;
#pragma unroll
        for (int nt = 0; nt < 8; nt++) {
            int col = n0 + wn + nt * 8 + 2 * tig;
            float bx = bias[col], by = bias[col + 1];
            float2 v0 = make_float2(acc[mt][nt][0] + bx, acc[mt][nt][1] + by);
            float2 v1 = make_float2(acc[mt][nt][2] + bx, acc[mt][nt][3] + by);
            *(float2*)&g_q[(size_t)row0 * N + col] = v0;
            *(float2*)&g_q[(size_t)(row0 + 8) * N + col] = v1;
        }
    }
}

// ---------------------------------------------------------------------------
// state = hidden
// ---------------------------------------------------------------------------
__global__ void copy_state_kernel(const float* __restrict__ hidden)
{
    int idx = blockIdx.x * blockDim.x + threadIdx.x;
    float4 v = ((const float4*)hidden)[idx];
    ((float4*)g_state)[idx] = v;
}

// ---------------------------------------------------------------------------
// Tiled dots: block = 24 nodes (+8 halo rows). nsq + dots[d=1..8].
// ---------------------------------------------------------------------------
#define DT 24
#define DROWS 32

__global__ __launch_bounds__(256) void dots_tiled_kernel()
{
    extern __shared__ float sh[];  // DROWS * HH
    int tid = threadIdx.x;
    int b = blockIdx.y;
    int i0 = blockIdx.x * DT;

#pragma unroll
    for (int r = 0; r < DROWS; r++) {
        int i = i0 + r;
        if (i < SS)
            ((float4*)(sh + (size_t)r * HH))[tid] =
                ((const float4*)(g_state + ((size_t)b * SS + i) * HH))[tid];
    }
    __syncthreads();

    int w = tid >> 5, lane = tid & 31;
#pragma unroll
    for (int nn = 0; nn < 3; nn++) {
        int ln = w * 3 + nn;          // 0..23
        int i = i0 + ln;
        if (i >= SS) continue;
        const float4* arow = (const float4*)(sh + (size_t)ln * HH);
        float4 a[8];
#pragma unroll
        for (int r = 0; r < 8; r++) a[r] = arow[lane + 32 * r];

#pragma unroll
        for (int d = 0; d <= RAD; d++) {
            if (d > 0 && i + d >= SS) break;
            float sum = 0.f;
            if (d == 0) {
#pragma unroll
                for (int r = 0; r < 8; r++)
                    sum += a[r].x*a[r].x + a[r].y*a[r].y + a[r].z*a[r].z + a[r].w*a[r].w;
            } else {
                const float4* crow = (const float4*)(sh + (size_t)(ln + d) * HH);
#pragma unroll
                for (int r = 0; r < 8; r++) {
                    float4 c = crow[lane + 32 * r];
                    sum += a[r].x*c.x + a[r].y*c.y + a[r].z*c.z + a[r].w*c.w;
                }
            }
#pragma unroll
            for (int o = 16; o > 0; o >>= 1)
                sum += __shfl_xor_sync(0xffffffffu, sum, o);
            if (lane == 0) {
                if (d == 0) g_nsq[b * SS + i] = sum;
                else g_dots[((size_t)b * RAD + (d - 1)) * SS + i] = sum;
            }
        }
    }
}

// ---------------------------------------------------------------------------
// mu: thread per edge, weights in smem, GELU saturation fast-path.
// ---------------------------------------------------------------------------
__global__ __launch_bounds__(256) void mu_kernel2(
    const float* __restrict__ W1, const float* __restrict__ b1,
    const float* __restrict__ W2, const float* __restrict__ b2)
{
    __shared__ float w1a[INNERD], w1b[INNERD], bb1[INNERD], w2s[INNERD];
    int tid = threadIdx.x;
    for (int k = tid; k < INNERD; k += 256) {
        w1a[k] = W1[k];
        w1b[k] = W1[INNERD + k];
        bb1[k] = b1[k];
        w2s[k] = W2[k];
    }
    __syncthreads();

    int e = blockIdx.x * 256 + tid;            // < BB*RAD*SS
    int b = e >> 14;
    int r = e & 16383;
    int d = (r >> 11) + 1;
    int i = r & 2047;
    size_t slot = ((size_t)b * RAD + (d - 1)) * SS + i;
    if (i + d >= SS) { g_mu[slot] = 0.f; return; }

    float nsqi = g_nsq[b * SS + i];
    float nsqj = g_nsq[b * SS + i + d];
    float dot  = g_dots[slot];
    float dist = sqrtf(fmaxf(nsqi + nsqj - 2.f * dot, 0.f));
    float ni = fmaxf(sqrtf(nsqi), 1e-6f);
    float nj = fmaxf(sqrtf(nsqj), 1e-6f);
    float cosv = dot / (ni * nj);

    float z = 0.f;
#pragma unroll 2
    for (int k = 0; k < INNERD; k += 4) {
        float4 wa = *(const float4*)&w1a[k];
        float4 wb = *(const float4*)&w1b[k];
        float4 bv = *(const float4*)&bb1[k];
        float4 w2v = *(const float4*)&w2s[k];
        float x0 = fmaf(dist, wa.x, fmaf(cosv, wb.x, bv.x));
        float x1 = fmaf(dist, wa.y, fmaf(cosv, wb.y, bv.y));
        float x2 = fmaf(dist, wa.z, fmaf(cosv, wb.z, bv.z));
        float x3 = fmaf(dist, wa.w, fmaf(cosv, wb.w, bv.w));
        float g0 = fmaxf(x0, 0.f);
        float g1 = fmaxf(x1, 0.f);
        float g2 = fmaxf(x2, 0.f);
        float g3 = fmaxf(x3, 0.f);
        if (fabsf(x0) < 6.f) g0 = 0.5f*x0*(1.f + erff(x0 * 0.70710678118654752f));
        if (fabsf(x1) < 6.f) g1 = 0.5f*x1*(1.f + erff(x1 * 0.70710678118654752f));
        if (fabsf(x2) < 6.f) g2 = 0.5f*x2*(1.f + erff(x2 * 0.70710678118654752f));
        if (fabsf(x3) < 6.f) g3 = 0.5f*x3*(1.f + erff(x3 * 0.70710678118654752f));
        z = fmaf(g0, w2v.x, z);
        z = fmaf(g1, w2v.y, z);
        z = fmaf(g2, w2v.z, z);
        z = fmaf(g3, w2v.w, z);
    }
    z += b2[0];
    float sp = fmaxf(z, 0.f) + log1pf(expf(-fabsf(z)));
    g_mu[slot] = fminf(sp + 1e-5f, MU_MAXV);
}

// ---------------------------------------------------------------------------
// deg -> isq
// ---------------------------------------------------------------------------
__global__ void deg_kernel()
{
    int i = blockIdx.x * blockDim.x + threadIdx.x;
    int b = blockIdx.y;
    if (i >= SS) return;
    float deg = 0.f;
#pragma unroll
    for (int d = 1; d <= RAD; d++) {
        if (i + d < SS) deg += g_mu[((size_t)b * RAD + (d - 1)) * SS + i];
        if (i >= d)     deg += g_mu[((size_t)b * RAD + (d - 1)) * SS + i - d];
    }
    g_isq[b * SS + i] = 1.f / sqrtf(fmaxf(deg, 1e-6f));
}

// ---------------------------------------------------------------------------
// Fused lap+update+smooth with halo recompute.
// Tile = 16 output rows; state rows [i0-9, i0+25) (34), tmp rows [i0-1, i0+17) (18).
// ---------------------------------------------------------------------------
#define LT 16
#define LSROWS 34
#define LTROWS 18

__global__ __launch_bounds__(256) void lapsmooth_kernel(float eta)
{
    extern __shared__ float sh[];
    float* st  = sh;                                 // LSROWS * HH
    float* tp  = st + (size_t)LSROWS * HH;           // LTROWS * HH
    float* cof = tp + (size_t)LTROWS * HH;           // LTROWS * 16
    float* csm = cof + LTROWS * 16;                  // LTROWS

    int tid = threadIdx.x;
    int b = blockIdx.y;
    int i0 = blockIdx.x * LT;

    // load state rows [i0-9, i0+25)
#pragma unroll
    for (int r = 0; r < LSROWS; r++) {
        int j = i0 - 9 + r;
        if (j >= 0 && j < SS)
            ((float4*)(st + (size_t)r * HH))[tid] =
                ((const float4*)(g_state + ((size_t)b * SS + j) * HH))[tid];
    }
    // coefficients for 18 tmp rows (clamped j)
    for (int idx = tid; idx < LTROWS * 16; idx += 256) {
        int jl = idx >> 4;
        int k = idx & 15;
        int j = i0 - 1 + jl;
        int je = min(max(j, 0), SS - 1);
        int d = (k >> 1) + 1;
        float c = 0.f;
        if (!(k & 1)) {                       // + direction
            int jn = je + d;
            if (jn < SS)
                c = g_mu[((size_t)b * RAD + (d - 1)) * SS + je] *
                    g_isq[b * SS + je] * g_isq[b * SS + jn];
        } else {                              // - direction
            int jn = je - d;
            if (jn >= 0)
                c = g_mu[((size_t)b * RAD + (d - 1)) * SS + jn] *
                    g_isq[b * SS + je] * g_isq[b * SS + jn];
        }
        cof[idx] = c;
    }
    __syncthreads();
    if (tid < LTROWS) {
        float s = 0.f;
#pragma unroll
        for (int k = 0; k < 16; k++) s += cof[tid * 16 + k];
        csm[tid] = s;
    }
    __syncthreads();

    // tmp rows
#pragma unroll
    for (int jl = 0; jl < LTROWS; jl++) {
        int j = i0 - 1 + jl;
        int je = min(max(j, 0), SS - 1);
        int jloc = je - i0 + 9;              // local state index
        float4 si = ((const float4*)(st + (size_t)jloc * HH))[tid];
        float cs = csm[jl];
        float4 acc;
        acc.x = cs * si.x; acc.y = cs * si.y; acc.z = cs * si.z; acc.w = cs * si.w;
#pragma unroll
        for (int k = 0; k < 16; k++) {
            float c = cof[jl * 16 + k];
            if (c != 0.f) {
                int d = (k >> 1) + 1;
                int off = (k & 1) ? -d : d;
                float4 sj = ((const float4*)(st + (size_t)(jloc + off) * HH))[tid];
                acc.x = fmaf(-c, sj.x, acc.x);
                acc.y = fmaf(-c, sj.y, acc.y);
                acc.z = fmaf(-c, sj.z, acc.z);
                acc.w = fmaf(-c, sj.w, acc.w);
            }
        }
        float4 qv = ((const float4*)(g_q + ((size_t)b * SS + je) * HH))[tid];
        float4 tv;
        tv.x = si.x - eta * (acc.x - qv.x);
        tv.y = si.y - eta * (acc.y - qv.y);
        tv.z = si.z - eta * (acc.z - qv.z);
        tv.w = si.w - eta * (acc.w - qv.w);
        ((float4*)(tp + (size_t)jl * HH))[tid] = tv;
    }
    __syncthreads();

    // smooth + writeback
#pragma unroll
    for (int il = 0; il < LT; il++) {
        int i = i0 + il;
        if (i >= SS) break;
        int jl = il + 1;
        float4 s = ((const float4*)(tp + (size_t)jl * HH))[tid];
        float4 l = ((const float4*)(tp + (size_t)(jl - 1) * HH))[tid];
        float4 r = ((const float4*)(tp + (size_t)(jl + 1) * HH))[tid];
        float4 o;
        o.x = s.x - LAMv * (2.f * s.x - l.x - r.x);
        o.y = s.y - LAMv * (2.f * s.y - l.y - r.y);
        o.z = s.z - LAMv * (2.f * s.z - l.z - r.z);
        o.w = s.w - LAMv * (2.f * s.w - l.w - r.w);
        ((float4*)(g_state + ((size_t)b * SS + i) * HH))[tid] = o;
    }
}

// ---------------------------------------------------------------------------
// energy[b] = 0.5 * sum_e mu_e * (nsq_i + nsq_j - 2 dot_e)
// ---------------------------------------------------------------------------
__global__ __launch_bounds__(256) void energy_kernel(float* __restrict__ out)
{
    int b = blockIdx.x;
    int tid = threadIdx.x;
    float partial = 0.f;
    for (int e = tid; e < RAD * SS; e += 256) {
        int d = e >> 11;
        int i = e & 2047;
        if (i + d + 1 < SS) {
            size_t slot = ((size_t)b * RAD + d) * SS + i;
            float mu = g_mu[slot];
            float dsq = g_nsq[b * SS + i] + g_nsq[b * SS + i + d + 1]
                      - 2.f * g_dots[slot];
            partial += mu * dsq;
        }
    }
#pragma unroll
    for (int o = 16; o > 0; o >>= 1)
        partial += __shfl_xor_sync(0xffffffffu, partial, o);
    __shared__ float red[8];
    int wid = tid >> 5, lane = tid & 31;
    if (lane == 0) red[wid] = partial;
    __syncthreads();
    if (tid == 0) {
        float s = 0.f;
#pragma unroll
        for (int w = 0; w < 8; w++) s += red[w];
        out[(size_t)BSH + b] = 0.5f * s;
    }
}

// ---------------------------------------------------------------------------
// out = layernorm(state + hidden) * gamma + beta
// ---------------------------------------------------------------------------
__global__ __launch_bounds__(256) void ln_kernel(
    const float* __restrict__ hidden,
    const float* __restrict__ gamma, const float* __restrict__ beta,
    float* __restrict__ out)
{
    int i = blockIdx.x, b = blockIdx.y;
    int tid = threadIdx.x;
    size_t base = ((size_t)b * SS + i) * HH + tid * 4;
    float4 s = *(const float4*)&g_state[base];
    float4 h = *(const float4*)&hidden[base];
    float4 x;
    x.x = s.x + h.x; x.y = s.y + h.y; x.z = s.z + h.z; x.w = s.w + h.w;
    float sum = x.x + x.y + x.z + x.w;
    float sq  = x.x*x.x + x.y*x.y + x.z*x.z + x.w*x.w;
#pragma unroll
    for (int o = 16; o > 0; o >>= 1) {
        sum += __shfl_xor_sync(0xffffffffu, sum, o);
        sq  += __shfl_xor_sync(0xffffffffu, sq,  o);
    }
    __shared__ float rs[8], rq[8];
    int wid = tid >> 5, lane = tid & 31;
    if (lane == 0) { rs[wid] = sum; rq[wid] = sq; }
    __syncthreads();
    __shared__ float s_mean, s_rstd;
    if (tid == 0) {
        float ts = 0.f, tq = 0.f;
#pragma unroll
        for (int w = 0; w < 8; w++) { ts += rs[w]; tq += rq[w]; }
        float mean = ts / HH;
        float var = tq / HH - mean * mean;
        s_mean = mean;
        s_rstd = rsqrtf(var + 1e-5f);
    }
    __syncthreads();
    float mean = s_mean, rstd = s_rstd;
    int hbase = tid * 4;
    float4 o;
    o.x = (x.x - mean) * rstd * gamma[hbase+0] + beta[hbase+0];
    o.y = (x.y - mean) * rstd * gamma[hbase+1] + beta[hbase+1];
    o.z = (x.z - mean) * rstd * gamma[hbase+2] + beta[hbase+2];
    o.w = (x.w - mean) * rstd * gamma[hbase+3] + beta[hbase+3];
    *(float4*)&out[base] = o;
}

// ---------------------------------------------------------------------------
extern "C" void kernel_launch(void* const* d_in, const int* in_sizes, int n_in,
                              void* d_out, int out_size)
{
    const float* hidden = (const float*)d_in[0];
    const float* Wq = (const float*)d_in[3];
    const float* bq = (const float*)d_in[4];
    const float* W1 = (const float*)d_in[5];
    const float* b1 = (const float*)d_in[6];
    const float* W2 = (const float*)d_in[7];
    const float* b2 = (const float*)d_in[8];
    const float* gamma = (const float*)d_in[9];
    const float* beta  = (const float*)d_in[10];
    float* out = (float*)d_out;

    const int dots_smem = DROWS * HH * sizeof(float);                    // 128 KB
    const int laps_smem = ((size_t)LSROWS * HH + (size_t)LTROWS * HH +
                           LTROWS * 16 + LTROWS) * sizeof(float);        // ~210 KB
    cudaFuncSetAttribute(dots_tiled_kernel,
                         cudaFuncAttributeMaxDynamicSharedMemorySize, dots_smem);
    cudaFuncSetAttribute(lapsmooth_kernel,
                         cudaFuncAttributeMaxDynamicSharedMemorySize, laps_smem);

    gemm_tf32_kernel<<<dim3(HH / TN, (BB * SS) / TM), 256>>>(hidden, Wq, bq);
    copy_state_kernel<<<(BSH / 4) / 256, 256>>>(hidden);

    int dots_grid = (SS + DT - 1) / DT;   // 86
    float eta = 0.1f;
    for (int step = 0; step < KSTEPS; step++) {
        dots_tiled_kernel<<<dim3(dots_grid, BB), 256, dots_smem>>>();
        mu_kernel2<<<(BB * RAD * SS) / 256, 256>>>(W1, b1, W2, b2);
        deg_kernel<<<dim3(SS / 256, BB), 256>>>();
        lapsmooth_kernel<<<dim3(SS / LT, BB), 256, laps_smem>>>(eta);
        eta *= 0.9f;
    }
    dots_tiled_kernel<<<dim3(dots_grid, BB), 256, dots_smem>>>();  // final state
    energy_kernel<<<BB, 256>>>(out);
    ln_kernel<<<dim3(SS, BB), 256>>>(hidden, gamma, beta, out);
}